// round 2
// baseline (speedup 1.0000x reference)
#include <cuda_runtime.h>

#define D 2048
#define B 16

// Scratch (allocation-free rule: device globals)
__device__ float g_u[B * D];
__device__ float g_diag[B * D];

__device__ __forceinline__ float sigmoidf(float x) {
    return 1.0f / (1.0f + __expf(-x));
}

// Warp transpose-reduce: on entry, each lane holds partial sums v[0..31].
// On exit, lane l holds (in v[0]) the total over all 32 lanes of original index l.
__device__ __forceinline__ void treduce32(float (&v)[32], int lane) {
#pragma unroll
    for (int m = 16; m > 0; m >>= 1) {
#pragma unroll
        for (int t = 0; t < 16; t++) {
            if (t < m) {
                float lo = v[t];
                float hi = v[t + m];
                float send = (lane & m) ? lo : hi;
                float recv = __shfl_xor_sync(0xffffffffu, send, m);
                v[t] = (lane & m) ? (hi + recv) : (lo + recv);
            }
        }
    }
}

__device__ __forceinline__ void finalize_one(
    int b, int i, float dA, float dX,
    const float* __restrict__ xt, const float* __restrict__ h,
    const float* __restrict__ ba, const float* __restrict__ bx,
    const float* __restrict__ Lam)
{
    float rt = sigmoidf(dA + __ldg(ba + i));
    float it = sigmoidf(dX + __ldg(bx + i));
    // log_a = -softplus(-Lam) = -log1p(exp(-Lam))
    float la = -log1pf(__expf(-__ldg(Lam + i)));
    float t  = la * rt * 0.125f;          // /C, C=8
    float a  = __expf(t);
    // 1 - a^2 = -expm1(2t)  (cancellation-free)
    float om = -expm1f(2.0f * t);
    float u  = sqrtf(fmaxf(om, 0.0f)) * it * __ldg(xt + b * D + i);
    g_u[b * D + i]    = u;
    g_diag[b * D + i] = a * __ldg(h + b * D + i);
}

// Gates: rt = sigmoid(xt@Wa.T+ba), it = sigmoid(xt@Wx.T+bx), then u/diag.
// One column per warp, BOTH matrices, all 16 batches.
// Grid: 256 blocks x 256 threads (8 warps) -> 2048 warps (one per column).
__global__ __launch_bounds__(256) void gates_kernel(
    const float* __restrict__ xt, const float* __restrict__ h,
    const float* __restrict__ Wa, const float* __restrict__ Wx,
    const float* __restrict__ ba, const float* __restrict__ bx,
    const float* __restrict__ Lam)
{
    __shared__ float4 xs4[B * 128];   // 16 rows x 512 floats = 32 KB

    const int tid  = threadIdx.x;
    const int lane = tid & 31;
    const int warp = tid >> 5;
    const int i    = blockIdx.x * 8 + warp;

    // v[0..15]  = dotA for batches 0..15
    // v[16..31] = dotX for batches 0..15
    float v[32];
#pragma unroll
    for (int t = 0; t < 32; t++) v[t] = 0.0f;

    const float4* xt4 = reinterpret_cast<const float4*>(xt);

#pragma unroll 1
    for (int kt = 0; kt < D; kt += 512) {
        __syncthreads();
        // Stage xt tile [16][512] into smem (coalesced float4, 256 threads)
#pragma unroll
        for (int e = tid; e < B * 128; e += 256) {
            int b = e >> 7, c = e & 127;
            xs4[e] = xt4[b * (D / 4) + (kt >> 2) + c];
        }
        __syncthreads();

        const float4* wap = reinterpret_cast<const float4*>(Wa + (size_t)i * D + kt);
        const float4* wxp = reinterpret_cast<const float4*>(Wx + (size_t)i * D + kt);

#pragma unroll
        for (int m = 0; m < 4; m++) {
            const int idx = m * 32 + lane;
            float4 wa = __ldg(wap + idx);
            float4 wx = __ldg(wxp + idx);
#pragma unroll
            for (int b = 0; b < 16; b++) {
                float4 x = xs4[b * 128 + idx];
                v[b] = fmaf(wa.x, x.x, v[b]);
                v[b] = fmaf(wa.y, x.y, v[b]);
                v[b] = fmaf(wa.z, x.z, v[b]);
                v[b] = fmaf(wa.w, x.w, v[b]);

                v[16 + b] = fmaf(wx.x, x.x, v[16 + b]);
                v[16 + b] = fmaf(wx.y, x.y, v[16 + b]);
                v[16 + b] = fmaf(wx.z, x.z, v[16 + b]);
                v[16 + b] = fmaf(wx.w, x.w, v[16 + b]);
            }
        }
    }

    treduce32(v, lane);  // lane l<16: dotA(i, b=l); lane l>=16: dotX(i, b=l-16)
    float r = v[0];
    float p = __shfl_xor_sync(0xffffffffu, r, 16);  // the "other matrix" dot

    if (lane < 16) {
        finalize_one(lane, i, r, p, xt, h, ba, bx, Lam);
    }
}

// Writer: ht[b,i,j] = u[b,j] + (i==j)*diag[b,i].
// Block = (batch b, 16 consecutive rows i). u row held in registers
// (2 float4 / thread, 256 threads = 2048 floats). Streaming stores.
__global__ __launch_bounds__(256) void writer_kernel(float* __restrict__ out) {
    const int b   = blockIdx.y;
    const int i0  = blockIdx.x * 16;
    const int tid = threadIdx.x;

    const float4* u4 = reinterpret_cast<const float4*>(g_u + b * D);
    const float4  va = __ldg(u4 + tid);
    const float4  vb = __ldg(u4 + tid + 256);
    const float*  dg = g_diag + b * D;

    float* obase = out + ((size_t)b * D + (size_t)i0) * D;

#pragma unroll 4
    for (int r = 0; r < 16; r++) {
        const int i  = i0 + r;
        const float dv = __ldg(dg + i);
        float4 sa = va, sb = vb;
        const int q = i >> 2, c = i & 3;
        if (q == tid) {
            if      (c == 0) sa.x += dv;
            else if (c == 1) sa.y += dv;
            else if (c == 2) sa.z += dv;
            else             sa.w += dv;
        } else if (q - 256 == tid) {
            if      (c == 0) sb.x += dv;
            else if (c == 1) sb.y += dv;
            else if (c == 2) sb.z += dv;
            else             sb.w += dv;
        }
        float4* orow = reinterpret_cast<float4*>(obase + (size_t)r * D);
        __stcs(orow + tid, sa);
        __stcs(orow + tid + 256, sb);
    }
}

extern "C" void kernel_launch(void* const* d_in, const int* in_sizes, int n_in,
                              void* d_out, int out_size) {
    const float* xt  = (const float*)d_in[0];
    const float* h   = (const float*)d_in[1];
    const float* Wa  = (const float*)d_in[2];
    const float* Wx  = (const float*)d_in[3];
    const float* ba  = (const float*)d_in[4];
    const float* bx  = (const float*)d_in[5];
    const float* Lam = (const float*)d_in[6];

    gates_kernel<<<256, 256>>>(xt, h, Wa, Wx, ba, bx, Lam);

    dim3 grid(D / 16, B);
    writer_kernel<<<grid, 256>>>((float*)d_out);
}

// round 3
// speedup vs baseline: 1.0334x; 1.0334x over previous
#include <cuda_runtime.h>

#define D 2048
#define B 16

// Scratch (allocation-free rule: device globals)
__device__ float g_u[B * D];
__device__ float g_diag[B * D];

__device__ __forceinline__ float sigmoidf(float x) {
    return 1.0f / (1.0f + __expf(-x));
}

// Warp transpose-reduce: on entry, each lane holds partial sums v[0..31]
// (v[t] = partial sum of logical index t). On exit, lane l holds in v[0]
// the total over all 32 lanes of logical index l.
__device__ __forceinline__ void treduce32(float (&v)[32], int lane) {
#pragma unroll
    for (int m = 16; m > 0; m >>= 1) {
#pragma unroll
        for (int t = 0; t < 16; t++) {
            if (t < m) {
                float lo = v[t];
                float hi = v[t + m];
                float send = (lane & m) ? lo : hi;
                float recv = __shfl_xor_sync(0xffffffffu, send, m);
                v[t] = (lane & m) ? (hi + recv) : (lo + recv);
            }
        }
    }
}

__device__ __forceinline__ void finalize_one(
    int b, int i, float dA, float dX,
    const float* __restrict__ xt, const float* __restrict__ h,
    const float* __restrict__ ba, const float* __restrict__ bx,
    const float* __restrict__ Lam)
{
    float rt = sigmoidf(dA + __ldg(ba + i));
    float it = sigmoidf(dX + __ldg(bx + i));
    // log_a = -softplus(-Lam) = -log1p(exp(-Lam))
    float la = -log1pf(__expf(-__ldg(Lam + i)));
    float t  = la * rt * 0.125f;          // /C, C=8
    float a  = __expf(t);
    // 1 - a^2 = -expm1(2t)  (cancellation-free)
    float om = -expm1f(2.0f * t);
    float u  = sqrtf(fmaxf(om, 0.0f)) * it * __ldg(xt + b * D + i);
    g_u[b * D + i]    = u;
    g_diag[b * D + i] = a * __ldg(h + b * D + i);
}

// Gates: rt = sigmoid(xt@Wa.T+ba), it = sigmoid(xt@Wx.T+bx), then u/diag.
// Each warp: 2 columns x 2 matrices x 8 batches  (LDS:FFMA = 1:16).
// Block = 256 threads (8 warps): warps 0-3 -> batches 0-7, warps 4-7 -> 8-15;
// warp w handles columns i0 = blockIdx.x*8 + (w&3)*2, i0+1.
// Grid: 256 blocks -> 2048 warps total.
__global__ __launch_bounds__(256) void gates_kernel(
    const float* __restrict__ xt, const float* __restrict__ h,
    const float* __restrict__ Wa, const float* __restrict__ Wx,
    const float* __restrict__ ba, const float* __restrict__ bx,
    const float* __restrict__ Lam)
{
    __shared__ float4 xs4[B * 128];   // 16 rows x 512 floats = 32 KB

    const int tid  = threadIdx.x;
    const int lane = tid & 31;
    const int warp = tid >> 5;
    const int bg   = warp >> 2;             // batch group: 0 -> b0..7, 1 -> b8..15
    const int i0   = blockIdx.x * 8 + (warp & 3) * 2;
    const int i1   = i0 + 1;

    // Logical accumulator layout (for treduce32):
    //  [ 0.. 7] = dotA(i0, b=bg*8+0..7)
    //  [ 8..15] = dotX(i0, b)
    //  [16..23] = dotA(i1, b)
    //  [24..31] = dotX(i1, b)
    float v[32];
#pragma unroll
    for (int t = 0; t < 32; t++) v[t] = 0.0f;

    const float4* xt4 = reinterpret_cast<const float4*>(xt);

#pragma unroll 1
    for (int kt = 0; kt < D; kt += 512) {
        __syncthreads();
        // Stage xt tile [16][512] into smem (coalesced float4, 256 threads)
#pragma unroll
        for (int e = tid; e < B * 128; e += 256) {
            int b = e >> 7, c = e & 127;
            xs4[e] = xt4[b * (D / 4) + (kt >> 2) + c];
        }
        __syncthreads();

        const float4* wa0p = reinterpret_cast<const float4*>(Wa + (size_t)i0 * D + kt);
        const float4* wa1p = reinterpret_cast<const float4*>(Wa + (size_t)i1 * D + kt);
        const float4* wx0p = reinterpret_cast<const float4*>(Wx + (size_t)i0 * D + kt);
        const float4* wx1p = reinterpret_cast<const float4*>(Wx + (size_t)i1 * D + kt);

        const float4* xbase = xs4 + bg * 8 * 128;

#pragma unroll
        for (int m = 0; m < 4; m++) {
            const int idx = m * 32 + lane;
            float4 wa0 = __ldg(wa0p + idx);
            float4 wa1 = __ldg(wa1p + idx);
            float4 wx0 = __ldg(wx0p + idx);
            float4 wx1 = __ldg(wx1p + idx);
#pragma unroll
            for (int b = 0; b < 8; b++) {
                float4 x = xbase[b * 128 + idx];

                v[b] = fmaf(wa0.x, x.x, v[b]);
                v[b] = fmaf(wa0.y, x.y, v[b]);
                v[b] = fmaf(wa0.z, x.z, v[b]);
                v[b] = fmaf(wa0.w, x.w, v[b]);

                v[8 + b] = fmaf(wx0.x, x.x, v[8 + b]);
                v[8 + b] = fmaf(wx0.y, x.y, v[8 + b]);
                v[8 + b] = fmaf(wx0.z, x.z, v[8 + b]);
                v[8 + b] = fmaf(wx0.w, x.w, v[8 + b]);

                v[16 + b] = fmaf(wa1.x, x.x, v[16 + b]);
                v[16 + b] = fmaf(wa1.y, x.y, v[16 + b]);
                v[16 + b] = fmaf(wa1.z, x.z, v[16 + b]);
                v[16 + b] = fmaf(wa1.w, x.w, v[16 + b]);

                v[24 + b] = fmaf(wx1.x, x.x, v[24 + b]);
                v[24 + b] = fmaf(wx1.y, x.y, v[24 + b]);
                v[24 + b] = fmaf(wx1.z, x.z, v[24 + b]);
                v[24 + b] = fmaf(wx1.w, x.w, v[24 + b]);
            }
        }
    }

    treduce32(v, lane);
    // lane l:   0..7  -> dotA(i0, b=bg*8+l)
    //           8..15 -> dotX(i0, b=bg*8+l-8)
    //          16..23 -> dotA(i1, b=bg*8+l-16)
    //          24..31 -> dotX(i1, b=bg*8+l-24)
    float r = v[0];
    float p = __shfl_xor_sync(0xffffffffu, r, 8);  // pair dotA with dotX

    if (lane < 8) {
        finalize_one(bg * 8 + lane, i0, r, p, xt, h, ba, bx, Lam);
    } else if (lane >= 16 && lane < 24) {
        finalize_one(bg * 8 + (lane - 16), i1, r, p, xt, h, ba, bx, Lam);
    }
}

// Writer: ht[b,i,j] = u[b,j] + (i==j)*diag[b,i].
// Block = (batch b, 16 consecutive rows i). u row held in registers
// (2 float4 / thread, 256 threads = 2048 floats). Streaming stores.
__global__ __launch_bounds__(256) void writer_kernel(float* __restrict__ out) {
    const int b   = blockIdx.y;
    const int i0  = blockIdx.x * 16;
    const int tid = threadIdx.x;

    const float4* u4 = reinterpret_cast<const float4*>(g_u + b * D);
    const float4  va = __ldg(u4 + tid);
    const float4  vb = __ldg(u4 + tid + 256);
    const float*  dg = g_diag + b * D;

    float* obase = out + ((size_t)b * D + (size_t)i0) * D;

#pragma unroll 4
    for (int r = 0; r < 16; r++) {
        const int i  = i0 + r;
        const float dv = __ldg(dg + i);
        float4 sa = va, sb = vb;
        const int q = i >> 2, c = i & 3;
        if (q == tid) {
            if      (c == 0) sa.x += dv;
            else if (c == 1) sa.y += dv;
            else if (c == 2) sa.z += dv;
            else             sa.w += dv;
        } else if (q - 256 == tid) {
            if      (c == 0) sb.x += dv;
            else if (c == 1) sb.y += dv;
            else if (c == 2) sb.z += dv;
            else             sb.w += dv;
        }
        float4* orow = reinterpret_cast<float4*>(obase + (size_t)r * D);
        __stcs(orow + tid, sa);
        __stcs(orow + tid + 256, sb);
    }
}

extern "C" void kernel_launch(void* const* d_in, const int* in_sizes, int n_in,
                              void* d_out, int out_size) {
    const float* xt  = (const float*)d_in[0];
    const float* h   = (const float*)d_in[1];
    const float* Wa  = (const float*)d_in[2];
    const float* Wx  = (const float*)d_in[3];
    const float* ba  = (const float*)d_in[4];
    const float* bx  = (const float*)d_in[5];
    const float* Lam = (const float*)d_in[6];

    gates_kernel<<<256, 256>>>(xt, h, Wa, Wx, ba, bx, Lam);

    dim3 grid(D / 16, B);
    writer_kernel<<<grid, 256>>>((float*)d_out);
}